// round 7
// baseline (speedup 1.0000x reference)
#include <cuda_runtime.h>
#include <cuda_fp16.h>
#include <cstdint>

#define EMBED    768
#define HEADS    6
#define HEAD_DIM 256
#define SEQ      128
#define BATCH    512
#define NTOK     (BATCH * SEQ)        // 65536
#define CATD     (HEADS * HEAD_DIM)   // 1536
#define QKVD     (3 * CATD)           // 4608
#define FFN      (4 * EMBED)          // 3072

// ================= helpers =================
__device__ __forceinline__ uint32_t packh2(float lo, float hi) {
    uint32_t r;
    asm("cvt.rn.f16x2.f32 %0, %1, %2;" : "=r"(r) : "f"(hi), "f"(lo));
    return r;
}
__device__ __forceinline__ void mma16816(float* c, const uint32_t* a, const uint32_t* b) {
    asm volatile(
        "mma.sync.aligned.m16n8k16.row.col.f32.f16.f16.f32 "
        "{%0,%1,%2,%3}, {%4,%5,%6,%7}, {%8,%9}, {%0,%1,%2,%3};"
        : "+f"(c[0]), "+f"(c[1]), "+f"(c[2]), "+f"(c[3])
        : "r"(a[0]), "r"(a[1]), "r"(a[2]), "r"(a[3]), "r"(b[0]), "r"(b[1]));
}

// GEMM tiling
#define TILE_NF  128
#define TILE_TK  256
#define KCH      32
#define HSTR     40
#define STG_H    ((TILE_TK + TILE_NF) * HSTR)          // halves per stage
#define GEMM_SMEM (2 * STG_H * 2)                      // 61440 B (2 stages)

// ================= scratch =================
__device__ __half g_hh  [(size_t)NTOK * EMBED];
__device__ __half g_qkv [(size_t)NTOK * QKVD];
__device__ __half g_oh  [(size_t)NTOK * CATD];
__device__ float  g_res [(size_t)NTOK * EMBED];
__device__ __half g_mid [(size_t)NTOK * FFN];
__device__ __half g_wqkv[(size_t)QKVD * EMBED];
__device__ __half g_wto [(size_t)EMBED * CATD];
__device__ __half g_wt1 [(size_t)FFN * EMBED];
__device__ __half g_wt2 [(size_t)EMBED * FFN];

// ================= transpose: in(k, n) -> out[n][k] (fp16 out) =================
__global__ __launch_bounds__(256) void transpose_k(
    const float* __restrict__ in, __half* __restrict__ out, int Kdim, int N, int Dh)
{
    __shared__ float t[32][33];
    const int k0 = blockIdx.y * 32;
    const int n0 = blockIdx.x * 32;
    const int tx = threadIdx.x, ty = threadIdx.y;

    #pragma unroll
    for (int i = 0; i < 4; i++) {
        const int k = k0 + ty + 8 * i;
        const int n = n0 + tx;
        const int h = n / Dh, d = n - h * Dh;
        t[ty + 8 * i][tx] = in[(size_t)h * Kdim * Dh + (size_t)k * Dh + d];
    }
    __syncthreads();
    #pragma unroll
    for (int i = 0; i < 4; i++) {
        out[(size_t)(n0 + ty + 8 * i) * Kdim + k0 + tx] = __float2half_rn(t[tx][ty + 8 * i]);
    }
}

// ================= LayerNorm (fp32 in -> fp16 out) =================
__global__ __launch_bounds__(256) void layernorm_k(
    const float* __restrict__ x, __half* __restrict__ y,
    const float* __restrict__ g, const float* __restrict__ b)
{
    const int row = blockIdx.x;
    const int tid = threadIdx.x;
    const float* xr = x + (size_t)row * EMBED;

    float v0 = xr[tid];
    float v1 = xr[tid + 256];
    float v2 = xr[tid + 512];

    float s = v0 + v1 + v2;
    float q = v0 * v0 + v1 * v1 + v2 * v2;

    #pragma unroll
    for (int o = 16; o; o >>= 1) {
        s += __shfl_xor_sync(0xffffffffu, s, o);
        q += __shfl_xor_sync(0xffffffffu, q, o);
    }
    __shared__ float ss[8], sq[8];
    const int w = tid >> 5, l = tid & 31;
    if (l == 0) { ss[w] = s; sq[w] = q; }
    __syncthreads();
    float S = 0.f, Q = 0.f;
    #pragma unroll
    for (int i = 0; i < 8; i++) { S += ss[i]; Q += sq[i]; }

    const float mu  = S * (1.0f / EMBED);
    const float var = Q * (1.0f / EMBED) - mu * mu;
    const float inv = rsqrtf(var + 1e-5f);

    __half* yr = y + (size_t)row * EMBED;
    yr[tid]       = __float2half_rn((v0 - mu) * inv * g[tid]       + b[tid]);
    yr[tid + 256] = __float2half_rn((v1 - mu) * inv * g[tid + 256] + b[tid + 256]);
    yr[tid + 512] = __float2half_rn((v2 - mu) * inv * g[tid + 512] + b[tid + 512]);
}

// ================= GEMM (fp16, 2-stage pipelined) =================
// C[m,n] = sum_k Hm[m,k]*Wt[n,k] (+bias)(relu)(+res)
template<bool OUT16, bool BIAS, bool RELU, bool RES>
__global__ __launch_bounds__(256) void gemm_tc(
    const __half* __restrict__ Wt,   // [Nout, K]  K-major fp16
    const __half* __restrict__ Hm,   // [NTOK, K]  fp16
    void* __restrict__ Cout,         // fp16 or fp32 [NTOK, Nout]
    int K, int Nout,
    const float* __restrict__ bias,
    const float* __restrict__ res)
{
    extern __shared__ char smem[];
    uint16_t* sbase = reinterpret_cast<uint16_t*>(smem);

    const int tid = threadIdx.x;
    const int wid = tid >> 5, lid = tid & 31;
    const int g = lid >> 2, t = lid & 3;
    const int wm = wid & 3;
    const int wn = wid >> 2;

    const int n0 = blockIdx.x * TILE_NF;
    const int m0 = blockIdx.y * TILE_TK;
    const int chunks = K / KCH;

    const __half* Ag = Hm + (size_t)m0 * K;
    const __half* Bg = Wt + (size_t)n0 * K;

    // per-thread ldg/sts coords
    const int arow = tid >> 2, aq = tid & 3;           // + 64-row steps

    float acc[4][8][4];
    #pragma unroll
    for (int i = 0; i < 4; i++)
        #pragma unroll
        for (int j = 0; j < 8; j++)
            #pragma unroll
            for (int r = 0; r < 4; r++) acc[i][j][r] = 0.f;

    uint4 pa[4], pb[2];

    #define LDG_CHUNK(kofs) do { \
        _Pragma("unroll") \
        for (int i = 0; i < 4; i++) \
            pa[i] = *reinterpret_cast<const uint4*>(Ag + (size_t)(arow + 64 * i) * K + (kofs) + aq * 8); \
        _Pragma("unroll") \
        for (int i = 0; i < 2; i++) \
            pb[i] = *reinterpret_cast<const uint4*>(Bg + (size_t)(arow + 64 * i) * K + (kofs) + aq * 8); \
    } while (0)

    #define STS_CHUNK(stg) do { \
        uint16_t* sA_ = sbase + (stg) * STG_H; \
        uint16_t* sB_ = sA_ + TILE_TK * HSTR; \
        _Pragma("unroll") \
        for (int i = 0; i < 4; i++) \
            *reinterpret_cast<uint4*>(sA_ + (arow + 64 * i) * HSTR + aq * 8) = pa[i]; \
        _Pragma("unroll") \
        for (int i = 0; i < 2; i++) \
            *reinterpret_cast<uint4*>(sB_ + (arow + 64 * i) * HSTR + aq * 8) = pb[i]; \
    } while (0)

    // prologue: chunk0 -> stage0; prefetch chunk1
    LDG_CHUNK(0);
    STS_CHUNK(0);
    if (chunks > 1) LDG_CHUNK(KCH);
    __syncthreads();

    for (int c = 0; c < chunks; c++) {
        // store prefetched chunk c+1 into the other stage (overlaps with MMAs below)
        if (c + 1 < chunks) STS_CHUNK((c + 1) & 1);
        // prefetch chunk c+2
        if (c + 2 < chunks) LDG_CHUNK((c + 2) * KCH);

        const uint16_t* sA = sbase + (c & 1) * STG_H;
        const uint16_t* sB = sA + TILE_TK * HSTR;

        #pragma unroll
        for (int ks = 0; ks < 2; ks++) {
            const int kb = ks * 16;
            uint32_t af[4][4];
            #pragma unroll
            for (int mt = 0; mt < 4; mt++) {
                const int rb = wm * 64 + mt * 16;
                af[mt][0] = *reinterpret_cast<const uint32_t*>(&sA[(rb + g)     * HSTR + kb + 2 * t]);
                af[mt][1] = *reinterpret_cast<const uint32_t*>(&sA[(rb + g + 8) * HSTR + kb + 2 * t]);
                af[mt][2] = *reinterpret_cast<const uint32_t*>(&sA[(rb + g)     * HSTR + kb + 2 * t + 8]);
                af[mt][3] = *reinterpret_cast<const uint32_t*>(&sA[(rb + g + 8) * HSTR + kb + 2 * t + 8]);
            }
            uint32_t bf[8][2];
            #pragma unroll
            for (int nt = 0; nt < 8; nt++) {
                const int cb = wn * 64 + nt * 8 + g;
                bf[nt][0] = *reinterpret_cast<const uint32_t*>(&sB[cb * HSTR + kb + 2 * t]);
                bf[nt][1] = *reinterpret_cast<const uint32_t*>(&sB[cb * HSTR + kb + 2 * t + 8]);
            }
            #pragma unroll
            for (int mt = 0; mt < 4; mt++)
                #pragma unroll
                for (int nt = 0; nt < 8; nt++)
                    mma16816(acc[mt][nt], af[mt], bf[nt]);
        }
        if (c + 1 < chunks) __syncthreads();
    }
    #undef LDG_CHUNK
    #undef STS_CHUNK

    float* C32 = reinterpret_cast<float*>(Cout);
    __half* C16 = reinterpret_cast<__half*>(Cout);

    #pragma unroll
    for (int mt = 0; mt < 4; mt++) {
        #pragma unroll
        for (int nt = 0; nt < 8; nt++) {
            const int col = n0 + wn * 64 + nt * 8 + 2 * t;
            float bx = 0.f, by = 0.f;
            if (BIAS) {
                const float2 b2 = *reinterpret_cast<const float2*>(bias + col);
                bx = b2.x; by = b2.y;
            }
            const int r1 = m0 + wm * 64 + mt * 16 + g;
            const int r2 = r1 + 8;

            float2 v1, v2;
            v1.x = acc[mt][nt][0] + bx; v1.y = acc[mt][nt][1] + by;
            v2.x = acc[mt][nt][2] + bx; v2.y = acc[mt][nt][3] + by;
            if (RELU) {
                v1.x = fmaxf(v1.x, 0.f); v1.y = fmaxf(v1.y, 0.f);
                v2.x = fmaxf(v2.x, 0.f); v2.y = fmaxf(v2.y, 0.f);
            }
            if (RES) {
                const float2 r1v = *reinterpret_cast<const float2*>(res + (size_t)r1 * Nout + col);
                const float2 r2v = *reinterpret_cast<const float2*>(res + (size_t)r2 * Nout + col);
                v1.x += r1v.x; v1.y += r1v.y;
                v2.x += r2v.x; v2.y += r2v.y;
            }
            if (OUT16) {
                *reinterpret_cast<uint32_t*>(C16 + (size_t)r1 * Nout + col) = packh2(v1.x, v1.y);
                *reinterpret_cast<uint32_t*>(C16 + (size_t)r2 * Nout + col) = packh2(v2.x, v2.y);
            } else {
                *reinterpret_cast<float2*>(C32 + (size_t)r1 * Nout + col) = v1;
                *reinterpret_cast<float2*>(C32 + (size_t)r2 * Nout + col) = v2;
            }
        }
    }
}

// ================= tensor-core causal attention =================
#define PSTR 136
#define QSTR 72
#define SSTR 132
#define VSTR 130
#define ATTN_SMEM (128 * PSTR * 2 + 128 * SSTR * 4)   // 102400

__global__ __launch_bounds__(256) void attention_k(
    const __half* __restrict__ qkv,   // [NTOK][4608]
    __half* __restrict__ o)           // [NTOK][1536]
{
    extern __shared__ char smem[];
    uint16_t* sP = reinterpret_cast<uint16_t*>(smem);
    char* ws = smem + 128 * PSTR * 2;
    uint16_t* sQ = reinterpret_cast<uint16_t*>(ws);
    uint16_t* sK = sQ + 128 * QSTR;
    float*    sS = reinterpret_cast<float*>(ws);
    uint16_t* sVt = reinterpret_cast<uint16_t*>(ws);

    const int tid = threadIdx.x;
    const int wid = tid >> 5, lid = tid & 31;
    const int g = lid >> 2, t = lid & 3;
    const int wm = wid & 3;
    const int wn = wid >> 2;

    const int bh = blockIdx.x;
    const int b  = bh / HEADS;
    const int h  = bh - b * HEADS;

    const __half* qbase = qkv + (size_t)(b * SEQ) * QKVD + h * HEAD_DIM;
    const __half* kbase = qbase + CATD;
    const __half* vbase = qbase + 2 * CATD;
    __half* obase = o + (size_t)(b * SEQ) * CATD + h * HEAD_DIM;

    // ---- S = Q K^T ----
    float acc[2][8][4];
    #pragma unroll
    for (int i = 0; i < 2; i++)
        #pragma unroll
        for (int j = 0; j < 8; j++)
            #pragma unroll
            for (int r = 0; r < 4; r++) acc[i][j][r] = 0.f;

    for (int c = 0; c < 4; c++) {
        #pragma unroll
        for (int i = 0; i < 4; i++) {
            const int idx = tid + 256 * i, row = idx >> 3, q = idx & 7;
            *reinterpret_cast<uint4*>(sQ + row * QSTR + q * 8) =
                *reinterpret_cast<const uint4*>(qbase + (size_t)row * QKVD + c * 64 + q * 8);
            *reinterpret_cast<uint4*>(sK + row * QSTR + q * 8) =
                *reinterpret_cast<const uint4*>(kbase + (size_t)row * QKVD + c * 64 + q * 8);
        }
        __syncthreads();

        #pragma unroll
        for (int ks = 0; ks < 4; ks++) {
            const int kb = ks * 16;
            uint32_t af[2][4];
            #pragma unroll
            for (int mt = 0; mt < 2; mt++) {
                const int rb = wm * 32 + mt * 16;
                af[mt][0] = *reinterpret_cast<const uint32_t*>(&sQ[(rb + g)     * QSTR + kb + 2 * t]);
                af[mt][1] = *reinterpret_cast<const uint32_t*>(&sQ[(rb + g + 8) * QSTR + kb + 2 * t]);
                af[mt][2] = *reinterpret_cast<const uint32_t*>(&sQ[(rb + g)     * QSTR + kb + 2 * t + 8]);
                af[mt][3] = *reinterpret_cast<const uint32_t*>(&sQ[(rb + g + 8) * QSTR + kb + 2 * t + 8]);
            }
            #pragma unroll
            for (int nt = 0; nt < 8; nt++) {
                if (wn * 64 + nt * 8 <= wm * 32 + 31) {
                    const int cb = wn * 64 + nt * 8 + g;
                    uint32_t bf[2];
                    bf[0] = *reinterpret_cast<const uint32_t*>(&sK[cb * QSTR + kb + 2 * t]);
                    bf[1] = *reinterpret_cast<const uint32_t*>(&sK[cb * QSTR + kb + 2 * t + 8]);
                    #pragma unroll
                    for (int mt = 0; mt < 2; mt++)
                        mma16816(acc[mt][nt], af[mt], bf);
                }
            }
        }
        __syncthreads();
    }

    // ---- scaled S -> smem ----
    const float scale = 0.03608439182435161f; // 768^-0.5
    #pragma unroll
    for (int mt = 0; mt < 2; mt++) {
        #pragma unroll
        for (int nt = 0; nt < 8; nt++) {
            const int col = wn * 64 + nt * 8 + 2 * t;
            const int r1 = wm * 32 + mt * 16 + g;
            float2 v1, v2;
            v1.x = acc[mt][nt][0] * scale; v1.y = acc[mt][nt][1] * scale;
            v2.x = acc[mt][nt][2] * scale; v2.y = acc[mt][nt][3] * scale;
            *reinterpret_cast<float2*>(sS + (r1)     * SSTR + col) = v1;
            *reinterpret_cast<float2*>(sS + (r1 + 8) * SSTR + col) = v2;
        }
    }
    __syncthreads();

    // ---- softmax rows, P -> fp16 ----
    if (tid < 128) {
        const int r = tid;
        float* row = sS + r * SSTR;
        float mx = row[0];
        for (int s = 1; s <= r; s++) mx = fmaxf(mx, row[s]);
        float sum = 0.f;
        for (int s = 0; s <= r; s++) {
            const float e = __expf(row[s] - mx);
            row[s] = e;
            sum += e;
        }
        const float inv = 1.0f / sum;
        uint16_t* prow = sP + r * PSTR;
        for (int s = 0; s <= r; s++) {
            const __half hv = __float2half_rn(row[s] * inv);
            prow[s] = *reinterpret_cast<const uint16_t*>(&hv);
        }
        for (int s = r + 1; s < 128; s++) prow[s] = 0;
    }
    __syncthreads();

    // ---- O = P V ----
    for (int c = 0; c < 4; c++) {
        #pragma unroll
        for (int i = 0; i < 16; i++) {
            const int id = tid + 256 * i;
            const int s = id >> 5, d2 = id & 31;
            const uint32_t v2 = *reinterpret_cast<const uint32_t*>(
                vbase + (size_t)s * QKVD + c * 64 + 2 * d2);
            sVt[(2 * d2)     * VSTR + s] = (uint16_t)(v2 & 0xffffu);
            sVt[(2 * d2 + 1) * VSTR + s] = (uint16_t)(v2 >> 16);
        }
        __syncthreads();

        float oacc[2][4][4];
        #pragma unroll
        for (int i = 0; i < 2; i++)
            #pragma unroll
            for (int j = 0; j < 4; j++)
                #pragma unroll
                for (int r = 0; r < 4; r++) oacc[i][j][r] = 0.f;

        #pragma unroll
        for (int ks = 0; ks < 8; ks++) {
            if (ks * 16 > wm * 32 + 31) break;
            const int kb = ks * 16;
            uint32_t af[2][4];
            #pragma unroll
            for (int mt = 0; mt < 2; mt++) {
                const int rb = wm * 32 + mt * 16;
                af[mt][0] = *reinterpret_cast<const uint32_t*>(&sP[(rb + g)     * PSTR + kb + 2 * t]);
                af[mt][1] = *reinterpret_cast<const uint32_t*>(&sP[(rb + g + 8) * PSTR + kb + 2 * t]);
                af[mt][2] = *reinterpret_cast<const uint32_t*>(&sP[(rb + g)     * PSTR + kb + 2 * t + 8]);
                af[mt][3] = *reinterpret_cast<const uint32_t*>(&sP[(rb + g + 8) * PSTR + kb + 2 * t + 8]);
            }
            #pragma unroll
            for (int nt = 0; nt < 4; nt++) {
                const int cb = wn * 32 + nt * 8 + g;
                uint32_t bf[2];
                bf[0] = *reinterpret_cast<const uint32_t*>(&sVt[cb * VSTR + kb + 2 * t]);
                bf[1] = *reinterpret_cast<const uint32_t*>(&sVt[cb * VSTR + kb + 2 * t + 8]);
                #pragma unroll
                for (int mt = 0; mt < 2; mt++)
                    mma16816(oacc[mt][nt], af[mt], bf);
            }
        }

        #pragma unroll
        for (int mt = 0; mt < 2; mt++) {
            #pragma unroll
            for (int nt = 0; nt < 4; nt++) {
                const int d = c * 64 + wn * 32 + nt * 8 + 2 * t;
                const int r1 = wm * 32 + mt * 16 + g;
                *reinterpret_cast<uint32_t*>(obase + (size_t)r1 * CATD + d) =
                    packh2(oacc[mt][nt][0], oacc[mt][nt][1]);
                *reinterpret_cast<uint32_t*>(obase + (size_t)(r1 + 8) * CATD + d) =
                    packh2(oacc[mt][nt][2], oacc[mt][nt][3]);
            }
        }
        __syncthreads();
    }
}

// ================= launch =================
extern "C" void kernel_launch(void* const* d_in, const int* in_sizes, int n_in,
                              void* d_out, int out_size)
{
    const float* x   = (const float*)d_in[0];
    const float* Wq  = (const float*)d_in[1];
    const float* Wk  = (const float*)d_in[2];
    const float* Wv  = (const float*)d_in[3];
    const float* Wo  = (const float*)d_in[4];
    const float* bo  = (const float*)d_in[5];
    const float* W1  = (const float*)d_in[6];
    const float* b1  = (const float*)d_in[7];
    const float* W2  = (const float*)d_in[8];
    const float* b2  = (const float*)d_in[9];
    const float* g1  = (const float*)d_in[10];
    const float* be1 = (const float*)d_in[11];
    const float* g2  = (const float*)d_in[12];
    const float* be2 = (const float*)d_in[13];
    float* out = (float*)d_out;

    void *phh, *pqkv, *poh, *pres, *pmid, *pwqkv, *pwto, *pwt1, *pwt2;
    cudaGetSymbolAddress(&phh,  g_hh);
    cudaGetSymbolAddress(&pqkv, g_qkv);
    cudaGetSymbolAddress(&poh,  g_oh);
    cudaGetSymbolAddress(&pres, g_res);
    cudaGetSymbolAddress(&pmid, g_mid);
    cudaGetSymbolAddress(&pwqkv, g_wqkv);
    cudaGetSymbolAddress(&pwto, g_wto);
    cudaGetSymbolAddress(&pwt1, g_wt1);
    cudaGetSymbolAddress(&pwt2, g_wt2);
    __half* H    = (__half*)phh;
    __half* QKV  = (__half*)pqkv;
    __half* O    = (__half*)poh;
    float*  R    = (float*)pres;
    __half* MID  = (__half*)pmid;
    __half* WQKV = (__half*)pwqkv;
    __half* WTO  = (__half*)pwto;
    __half* WT1  = (__half*)pwt1;
    __half* WT2  = (__half*)pwt2;

    cudaFuncSetAttribute(attention_k, cudaFuncAttributeMaxDynamicSharedMemorySize, ATTN_SMEM);
    cudaFuncSetAttribute(gemm_tc<true,  false, false, false>, cudaFuncAttributeMaxDynamicSharedMemorySize, GEMM_SMEM);
    cudaFuncSetAttribute(gemm_tc<false, true,  false, true >, cudaFuncAttributeMaxDynamicSharedMemorySize, GEMM_SMEM);
    cudaFuncSetAttribute(gemm_tc<true,  true,  true,  false>, cudaFuncAttributeMaxDynamicSharedMemorySize, GEMM_SMEM);

    dim3 tt(32, 8);
    transpose_k<<<dim3(CATD / 32, EMBED / 32), tt>>>(Wq, WQKV,                        EMBED, CATD, HEAD_DIM);
    transpose_k<<<dim3(CATD / 32, EMBED / 32), tt>>>(Wk, WQKV + (size_t)CATD * EMBED, EMBED, CATD, HEAD_DIM);
    transpose_k<<<dim3(CATD / 32, EMBED / 32), tt>>>(Wv, WQKV + (size_t)2 * CATD * EMBED, EMBED, CATD, HEAD_DIM);
    transpose_k<<<dim3(EMBED / 32, CATD / 32), tt>>>(Wo, WTO, CATD, EMBED, EMBED);
    transpose_k<<<dim3(FFN / 32, EMBED / 32),  tt>>>(W1, WT1, EMBED, FFN, FFN);
    transpose_k<<<dim3(EMBED / 32, FFN / 32),  tt>>>(W2, WT2, FFN, EMBED, EMBED);

    layernorm_k<<<NTOK, 256>>>(x, H, g1, be1);

    gemm_tc<true, false, false, false><<<dim3(QKVD / TILE_NF, NTOK / TILE_TK), 256, GEMM_SMEM>>>(
        WQKV, H, QKV, EMBED, QKVD, nullptr, nullptr);

    attention_k<<<BATCH * HEADS, 256, ATTN_SMEM>>>(QKV, O);

    gemm_tc<false, true, false, true><<<dim3(EMBED / TILE_NF, NTOK / TILE_TK), 256, GEMM_SMEM>>>(
        WTO, O, R, CATD, EMBED, bo, x);

    layernorm_k<<<NTOK, 256>>>(R, H, g2, be2);

    gemm_tc<true, true, true, false><<<dim3(FFN / TILE_NF, NTOK / TILE_TK), 256, GEMM_SMEM>>>(
        WT1, H, MID, EMBED, FFN, b1, nullptr);

    gemm_tc<false, true, false, true><<<dim3(EMBED / TILE_NF, NTOK / TILE_TK), 256, GEMM_SMEM>>>(
        WT2, MID, out, FFN, EMBED, b2, R);
}

// round 8
// speedup vs baseline: 1.1451x; 1.1451x over previous
#include <cuda_runtime.h>
#include <cuda_fp16.h>
#include <cstdint>

#define EMBED    768
#define HEADS    6
#define HEAD_DIM 256
#define SEQ      128
#define BATCH    512
#define NTOK     (BATCH * SEQ)        // 65536
#define CATD     (HEADS * HEAD_DIM)   // 1536
#define QKVD     (3 * CATD)           // 4608
#define FFN      (4 * EMBED)          // 3072

// ================= helpers =================
__device__ __forceinline__ uint32_t packh2(float lo, float hi) {
    uint32_t r;
    asm("cvt.rn.f16x2.f32 %0, %1, %2;" : "=r"(r) : "f"(hi), "f"(lo));
    return r;
}
__device__ __forceinline__ void mma16816(float* c, const uint32_t* a, const uint32_t* b) {
    asm volatile(
        "mma.sync.aligned.m16n8k16.row.col.f32.f16.f16.f32 "
        "{%0,%1,%2,%3}, {%4,%5,%6,%7}, {%8,%9}, {%0,%1,%2,%3};"
        : "+f"(c[0]), "+f"(c[1]), "+f"(c[2]), "+f"(c[3])
        : "r"(a[0]), "r"(a[1]), "r"(a[2]), "r"(a[3]), "r"(b[0]), "r"(b[1]));
}
__device__ __forceinline__ uint32_t smem_u32(const void* p) {
    uint32_t a;
    asm("{ .reg .u64 t; cvta.to.shared.u64 t, %1; cvt.u32.u64 %0, t; }" : "=r"(a) : "l"(p));
    return a;
}
#define CP_ASYNC16(saddr, gptr) \
    asm volatile("cp.async.cg.shared.global [%0], [%1], 16;" :: "r"(saddr), "l"(gptr))
#define CP_COMMIT() asm volatile("cp.async.commit_group;" ::: "memory")
#define CP_WAIT1()  asm volatile("cp.async.wait_group 1;" ::: "memory")

// GEMM tiling
#define TILE_NF  128
#define TILE_TK  256
#define KCH      32
#define HSTR     40
#define STAGES   3
#define STG_H    ((TILE_TK + TILE_NF) * HSTR)          // halves per stage
#define GEMM_SMEM (STAGES * STG_H * 2)                 // 92160 B

// ================= scratch =================
__device__ __half g_hh  [(size_t)NTOK * EMBED];
__device__ __half g_qkv [(size_t)NTOK * QKVD];
__device__ __half g_oh  [(size_t)NTOK * CATD];
__device__ float  g_res [(size_t)NTOK * EMBED];
__device__ __half g_mid [(size_t)NTOK * FFN];
__device__ __half g_wqkv[(size_t)QKVD * EMBED];
__device__ __half g_wto [(size_t)EMBED * CATD];
__device__ __half g_wt1 [(size_t)FFN * EMBED];
__device__ __half g_wt2 [(size_t)EMBED * FFN];

// ================= transpose: in(k, n) -> out[n][k] (fp16 out) =================
__global__ __launch_bounds__(256) void transpose_k(
    const float* __restrict__ in, __half* __restrict__ out, int Kdim, int N, int Dh)
{
    __shared__ float t[32][33];
    const int k0 = blockIdx.y * 32;
    const int n0 = blockIdx.x * 32;
    const int tx = threadIdx.x, ty = threadIdx.y;

    #pragma unroll
    for (int i = 0; i < 4; i++) {
        const int k = k0 + ty + 8 * i;
        const int n = n0 + tx;
        const int h = n / Dh, d = n - h * Dh;
        t[ty + 8 * i][tx] = in[(size_t)h * Kdim * Dh + (size_t)k * Dh + d];
    }
    __syncthreads();
    #pragma unroll
    for (int i = 0; i < 4; i++) {
        out[(size_t)(n0 + ty + 8 * i) * Kdim + k0 + tx] = __float2half_rn(t[tx][ty + 8 * i]);
    }
}

// ================= LayerNorm (fp32 in -> fp16 out) =================
__global__ __launch_bounds__(256) void layernorm_k(
    const float* __restrict__ x, __half* __restrict__ y,
    const float* __restrict__ g, const float* __restrict__ b)
{
    const int row = blockIdx.x;
    const int tid = threadIdx.x;
    const float* xr = x + (size_t)row * EMBED;

    float v0 = xr[tid];
    float v1 = xr[tid + 256];
    float v2 = xr[tid + 512];

    float s = v0 + v1 + v2;
    float q = v0 * v0 + v1 * v1 + v2 * v2;

    #pragma unroll
    for (int o = 16; o; o >>= 1) {
        s += __shfl_xor_sync(0xffffffffu, s, o);
        q += __shfl_xor_sync(0xffffffffu, q, o);
    }
    __shared__ float ss[8], sq[8];
    const int w = tid >> 5, l = tid & 31;
    if (l == 0) { ss[w] = s; sq[w] = q; }
    __syncthreads();
    float S = 0.f, Q = 0.f;
    #pragma unroll
    for (int i = 0; i < 8; i++) { S += ss[i]; Q += sq[i]; }

    const float mu  = S * (1.0f / EMBED);
    const float var = Q * (1.0f / EMBED) - mu * mu;
    const float inv = rsqrtf(var + 1e-5f);

    __half* yr = y + (size_t)row * EMBED;
    yr[tid]       = __float2half_rn((v0 - mu) * inv * g[tid]       + b[tid]);
    yr[tid + 256] = __float2half_rn((v1 - mu) * inv * g[tid + 256] + b[tid + 256]);
    yr[tid + 512] = __float2half_rn((v2 - mu) * inv * g[tid + 512] + b[tid + 512]);
}

// ================= GEMM (fp16, 3-stage cp.async pipeline) =================
// C[m,n] = sum_k Hm[m,k]*Wt[n,k] (+bias)(relu)(+res)
template<bool OUT16, bool BIAS, bool RELU, bool RES>
__global__ __launch_bounds__(256) void gemm_tc(
    const __half* __restrict__ Wt,   // [Nout, K]  K-major fp16
    const __half* __restrict__ Hm,   // [NTOK, K]  fp16
    void* __restrict__ Cout,         // fp16 or fp32 [NTOK, Nout]
    int K, int Nout,
    const float* __restrict__ bias,
    const float* __restrict__ res)
{
    extern __shared__ char smem[];
    uint16_t* sbase = reinterpret_cast<uint16_t*>(smem);
    const uint32_t sb32 = smem_u32(smem);

    const int tid = threadIdx.x;
    const int wid = tid >> 5, lid = tid & 31;
    const int g = lid >> 2, t = lid & 3;
    const int wm = wid & 3;
    const int wn = wid >> 2;

    const int n0 = blockIdx.x * TILE_NF;
    const int m0 = blockIdx.y * TILE_TK;
    const int chunks = K / KCH;

    const __half* Ag = Hm + (size_t)m0 * K;
    const __half* Bg = Wt + (size_t)n0 * K;

    const int arow = tid >> 2, aq = tid & 3;

    float acc[4][8][4];
    #pragma unroll
    for (int i = 0; i < 4; i++)
        #pragma unroll
        for (int j = 0; j < 8; j++)
            #pragma unroll
            for (int r = 0; r < 4; r++) acc[i][j][r] = 0.f;

    // issue one chunk's loads into a stage (6 x cp.async 16B per thread)
    #define ISSUE_CHUNK(chunk, stg) do { \
        const int kofs_ = (chunk) * KCH; \
        const uint32_t sA_ = sb32 + (stg) * STG_H * 2; \
        const uint32_t sB_ = sA_ + TILE_TK * HSTR * 2; \
        _Pragma("unroll") \
        for (int i = 0; i < 4; i++) \
            CP_ASYNC16(sA_ + ((arow + 64 * i) * HSTR + aq * 8) * 2, \
                       Ag + (size_t)(arow + 64 * i) * K + kofs_ + aq * 8); \
        _Pragma("unroll") \
        for (int i = 0; i < 2; i++) \
            CP_ASYNC16(sB_ + ((arow + 64 * i) * HSTR + aq * 8) * 2, \
                       Bg + (size_t)(arow + 64 * i) * K + kofs_ + aq * 8); \
    } while (0)

    // prologue: stages 0..STAGES-2
    ISSUE_CHUNK(0, 0); CP_COMMIT();
    if (chunks > 1) { ISSUE_CHUNK(1, 1); } CP_COMMIT();

    for (int c = 0; c < chunks; c++) {
        CP_WAIT1();            // chunk c resident
        __syncthreads();       // all warps done reading the slot we're about to overwrite

        if (c + STAGES - 1 < chunks) { ISSUE_CHUNK(c + STAGES - 1, (c + STAGES - 1) % STAGES); }
        CP_COMMIT();

        const uint16_t* sA = sbase + (c % STAGES) * STG_H;
        const uint16_t* sB = sA + TILE_TK * HSTR;

        #pragma unroll
        for (int ks = 0; ks < 2; ks++) {
            const int kb = ks * 16;
            uint32_t af[4][4];
            #pragma unroll
            for (int mt = 0; mt < 4; mt++) {
                const int rb = wm * 64 + mt * 16;
                af[mt][0] = *reinterpret_cast<const uint32_t*>(&sA[(rb + g)     * HSTR + kb + 2 * t]);
                af[mt][1] = *reinterpret_cast<const uint32_t*>(&sA[(rb + g + 8) * HSTR + kb + 2 * t]);
                af[mt][2] = *reinterpret_cast<const uint32_t*>(&sA[(rb + g)     * HSTR + kb + 2 * t + 8]);
                af[mt][3] = *reinterpret_cast<const uint32_t*>(&sA[(rb + g + 8) * HSTR + kb + 2 * t + 8]);
            }
            uint32_t bf[8][2];
            #pragma unroll
            for (int nt = 0; nt < 8; nt++) {
                const int cb = wn * 64 + nt * 8 + g;
                bf[nt][0] = *reinterpret_cast<const uint32_t*>(&sB[cb * HSTR + kb + 2 * t]);
                bf[nt][1] = *reinterpret_cast<const uint32_t*>(&sB[cb * HSTR + kb + 2 * t + 8]);
            }
            #pragma unroll
            for (int mt = 0; mt < 4; mt++)
                #pragma unroll
                for (int nt = 0; nt < 8; nt++)
                    mma16816(acc[mt][nt], af[mt], bf[nt]);
        }
    }
    #undef ISSUE_CHUNK

    float* C32 = reinterpret_cast<float*>(Cout);
    __half* C16 = reinterpret_cast<__half*>(Cout);

    #pragma unroll
    for (int mt = 0; mt < 4; mt++) {
        #pragma unroll
        for (int nt = 0; nt < 8; nt++) {
            const int col = n0 + wn * 64 + nt * 8 + 2 * t;
            float bx = 0.f, by = 0.f;
            if (BIAS) {
                const float2 b2 = *reinterpret_cast<const float2*>(bias + col);
                bx = b2.x; by = b2.y;
            }
            const int r1 = m0 + wm * 64 + mt * 16 + g;
            const int r2 = r1 + 8;

            float2 v1, v2;
            v1.x = acc[mt][nt][0] + bx; v1.y = acc[mt][nt][1] + by;
            v2.x = acc[mt][nt][2] + bx; v2.y = acc[mt][nt][3] + by;
            if (RELU) {
                v1.x = fmaxf(v1.x, 0.f); v1.y = fmaxf(v1.y, 0.f);
                v2.x = fmaxf(v2.x, 0.f); v2.y = fmaxf(v2.y, 0.f);
            }
            if (RES) {
                const float2 r1v = *reinterpret_cast<const float2*>(res + (size_t)r1 * Nout + col);
                const float2 r2v = *reinterpret_cast<const float2*>(res + (size_t)r2 * Nout + col);
                v1.x += r1v.x; v1.y += r1v.y;
                v2.x += r2v.x; v2.y += r2v.y;
            }
            if (OUT16) {
                *reinterpret_cast<uint32_t*>(C16 + (size_t)r1 * Nout + col) = packh2(v1.x, v1.y);
                *reinterpret_cast<uint32_t*>(C16 + (size_t)r2 * Nout + col) = packh2(v2.x, v2.y);
            } else {
                *reinterpret_cast<float2*>(C32 + (size_t)r1 * Nout + col) = v1;
                *reinterpret_cast<float2*>(C32 + (size_t)r2 * Nout + col) = v2;
            }
        }
    }
}

// ================= tensor-core causal attention =================
#define PSTR 136
#define QSTR 72
#define SSTR 132
#define VSTR 130
#define ATTN_SMEM (128 * PSTR * 2 + 128 * SSTR * 4)   // 102400

__global__ __launch_bounds__(256) void attention_k(
    const __half* __restrict__ qkv,   // [NTOK][4608]
    __half* __restrict__ o)           // [NTOK][1536]
{
    extern __shared__ char smem[];
    uint16_t* sP = reinterpret_cast<uint16_t*>(smem);
    char* ws = smem + 128 * PSTR * 2;
    uint16_t* sQ = reinterpret_cast<uint16_t*>(ws);
    uint16_t* sK = sQ + 128 * QSTR;
    float*    sS = reinterpret_cast<float*>(ws);
    uint16_t* sVt = reinterpret_cast<uint16_t*>(ws);

    const int tid = threadIdx.x;
    const int wid = tid >> 5, lid = tid & 31;
    const int g = lid >> 2, t = lid & 3;
    const int wm = wid & 3;
    const int wn = wid >> 2;

    const int bh = blockIdx.x;
    const int b  = bh / HEADS;
    const int h  = bh - b * HEADS;

    const __half* qbase = qkv + (size_t)(b * SEQ) * QKVD + h * HEAD_DIM;
    const __half* kbase = qbase + CATD;
    const __half* vbase = qbase + 2 * CATD;
    __half* obase = o + (size_t)(b * SEQ) * CATD + h * HEAD_DIM;

    // ---- S = Q K^T ----
    float acc[2][8][4];
    #pragma unroll
    for (int i = 0; i < 2; i++)
        #pragma unroll
        for (int j = 0; j < 8; j++)
            #pragma unroll
            for (int r = 0; r < 4; r++) acc[i][j][r] = 0.f;

    for (int c = 0; c < 4; c++) {
        #pragma unroll
        for (int i = 0; i < 4; i++) {
            const int idx = tid + 256 * i, row = idx >> 3, q = idx & 7;
            *reinterpret_cast<uint4*>(sQ + row * QSTR + q * 8) =
                *reinterpret_cast<const uint4*>(qbase + (size_t)row * QKVD + c * 64 + q * 8);
            *reinterpret_cast<uint4*>(sK + row * QSTR + q * 8) =
                *reinterpret_cast<const uint4*>(kbase + (size_t)row * QKVD + c * 64 + q * 8);
        }
        __syncthreads();

        #pragma unroll
        for (int ks = 0; ks < 4; ks++) {
            const int kb = ks * 16;
            uint32_t af[2][4];
            #pragma unroll
            for (int mt = 0; mt < 2; mt++) {
                const int rb = wm * 32 + mt * 16;
                af[mt][0] = *reinterpret_cast<const uint32_t*>(&sQ[(rb + g)     * QSTR + kb + 2 * t]);
                af[mt][1] = *reinterpret_cast<const uint32_t*>(&sQ[(rb + g + 8) * QSTR + kb + 2 * t]);
                af[mt][2] = *reinterpret_cast<const uint32_t*>(&sQ[(rb + g)     * QSTR + kb + 2 * t + 8]);
                af[mt][3] = *reinterpret_cast<const uint32_t*>(&sQ[(rb + g + 8) * QSTR + kb + 2 * t + 8]);
            }
            #pragma unroll
            for (int nt = 0; nt < 8; nt++) {
                if (wn * 64 + nt * 8 <= wm * 32 + 31) {
                    const int cb = wn * 64 + nt * 8 + g;
                    uint32_t bf[2];
                    bf[0] = *reinterpret_cast<const uint32_t*>(&sK[cb * QSTR + kb + 2 * t]);
                    bf[1] = *reinterpret_cast<const uint32_t*>(&sK[cb * QSTR + kb + 2 * t + 8]);
                    #pragma unroll
                    for (int mt = 0; mt < 2; mt++)
                        mma16816(acc[mt][nt], af[mt], bf);
                }
            }
        }
        __syncthreads();
    }

    // ---- scaled S -> smem ----
    const float scale = 0.03608439182435161f; // 768^-0.5
    #pragma unroll
    for (int mt = 0; mt < 2; mt++) {
        #pragma unroll
        for (int nt = 0; nt < 8; nt++) {
            const int col = wn * 64 + nt * 8 + 2 * t;
            const int r1 = wm * 32 + mt * 16 + g;
            float2 v1, v2;
            v1.x = acc[mt][nt][0] * scale; v1.y = acc[mt][nt][1] * scale;
            v2.x = acc[mt][nt][2] * scale; v2.y = acc[mt][nt][3] * scale;
            *reinterpret_cast<float2*>(sS + (r1)     * SSTR + col) = v1;
            *reinterpret_cast<float2*>(sS + (r1 + 8) * SSTR + col) = v2;
        }
    }
    __syncthreads();

    // ---- softmax rows, P -> fp16 ----
    if (tid < 128) {
        const int r = tid;
        float* row = sS + r * SSTR;
        float mx = row[0];
        for (int s = 1; s <= r; s++) mx = fmaxf(mx, row[s]);
        float sum = 0.f;
        for (int s = 0; s <= r; s++) {
            const float e = __expf(row[s] - mx);
            row[s] = e;
            sum += e;
        }
        const float inv = 1.0f / sum;
        uint16_t* prow = sP + r * PSTR;
        for (int s = 0; s <= r; s++) {
            const __half hv = __float2half_rn(row[s] * inv);
            prow[s] = *reinterpret_cast<const uint16_t*>(&hv);
        }
        for (int s = r + 1; s < 128; s++) prow[s] = 0;
    }
    __syncthreads();

    // ---- O = P V ----
    for (int c = 0; c < 4; c++) {
        #pragma unroll
        for (int i = 0; i < 16; i++) {
            const int id = tid + 256 * i;
            const int s = id >> 5, d2 = id & 31;
            const uint32_t v2 = *reinterpret_cast<const uint32_t*>(
                vbase + (size_t)s * QKVD + c * 64 + 2 * d2);
            sVt[(2 * d2)     * VSTR + s] = (uint16_t)(v2 & 0xffffu);
            sVt[(2 * d2 + 1) * VSTR + s] = (uint16_t)(v2 >> 16);
        }
        __syncthreads();

        float oacc[2][4][4];
        #pragma unroll
        for (int i = 0; i < 2; i++)
            #pragma unroll
            for (int j = 0; j < 4; j++)
                #pragma unroll
                for (int r = 0; r < 4; r++) oacc[i][j][r] = 0.f;

        #pragma unroll
        for (int ks = 0; ks < 8; ks++) {
            if (ks * 16 > wm * 32 + 31) break;
            const int kb = ks * 16;
            uint32_t af[2][4];
            #pragma unroll
            for (int mt = 0; mt < 2; mt++) {
                const int rb = wm * 32 + mt * 16;
                af[mt][0] = *reinterpret_cast<const uint32_t*>(&sP[(rb + g)     * PSTR + kb + 2 * t]);
                af[mt][1] = *reinterpret_cast<const uint32_t*>(&sP[(rb + g + 8) * PSTR + kb + 2 * t]);
                af[mt][2] = *reinterpret_cast<const uint32_t*>(&sP[(rb + g)     * PSTR + kb + 2 * t + 8]);
                af[mt][3] = *reinterpret_cast<const uint32_t*>(&sP[(rb + g + 8) * PSTR + kb + 2 * t + 8]);
            }
            #pragma unroll
            for (int nt = 0; nt < 4; nt++) {
                const int cb = wn * 32 + nt * 8 + g;
                uint32_t bf[2];
                bf[0] = *reinterpret_cast<const uint32_t*>(&sVt[cb * VSTR + kb + 2 * t]);
                bf[1] = *reinterpret_cast<const uint32_t*>(&sVt[cb * VSTR + kb + 2 * t + 8]);
                #pragma unroll
                for (int mt = 0; mt < 2; mt++)
                    mma16816(oacc[mt][nt], af[mt], bf);
            }
        }

        #pragma unroll
        for (int mt = 0; mt < 2; mt++) {
            #pragma unroll
            for (int nt = 0; nt < 4; nt++) {
                const int d = c * 64 + wn * 32 + nt * 8 + 2 * t;
                const int r1 = wm * 32 + mt * 16 + g;
                *reinterpret_cast<uint32_t*>(obase + (size_t)r1 * CATD + d) =
                    packh2(oacc[mt][nt][0], oacc[mt][nt][1]);
                *reinterpret_cast<uint32_t*>(obase + (size_t)(r1 + 8) * CATD + d) =
                    packh2(oacc[mt][nt][2], oacc[mt][nt][3]);
            }
        }
        __syncthreads();
    }
}

// ================= launch =================
extern "C" void kernel_launch(void* const* d_in, const int* in_sizes, int n_in,
                              void* d_out, int out_size)
{
    const float* x   = (const float*)d_in[0];
    const float* Wq  = (const float*)d_in[1];
    const float* Wk  = (const float*)d_in[2];
    const float* Wv  = (const float*)d_in[3];
    const float* Wo  = (const float*)d_in[4];
    const float* bo  = (const float*)d_in[5];
    const float* W1  = (const float*)d_in[6];
    const float* b1  = (const float*)d_in[7];
    const float* W2  = (const float*)d_in[8];
    const float* b2  = (const float*)d_in[9];
    const float* g1  = (const float*)d_in[10];
    const float* be1 = (const float*)d_in[11];
    const float* g2  = (const float*)d_in[12];
    const float* be2 = (const float*)d_in[13];
    float* out = (float*)d_out;

    void *phh, *pqkv, *poh, *pres, *pmid, *pwqkv, *pwto, *pwt1, *pwt2;
    cudaGetSymbolAddress(&phh,  g_hh);
    cudaGetSymbolAddress(&pqkv, g_qkv);
    cudaGetSymbolAddress(&poh,  g_oh);
    cudaGetSymbolAddress(&pres, g_res);
    cudaGetSymbolAddress(&pmid, g_mid);
    cudaGetSymbolAddress(&pwqkv, g_wqkv);
    cudaGetSymbolAddress(&pwto, g_wto);
    cudaGetSymbolAddress(&pwt1, g_wt1);
    cudaGetSymbolAddress(&pwt2, g_wt2);
    __half* H    = (__half*)phh;
    __half* QKV  = (__half*)pqkv;
    __half* O    = (__half*)poh;
    float*  R    = (float*)pres;
    __half* MID  = (__half*)pmid;
    __half* WQKV = (__half*)pwqkv;
    __half* WTO  = (__half*)pwto;
    __half* WT1  = (__half*)pwt1;
    __half* WT2  = (__half*)pwt2;

    cudaFuncSetAttribute(attention_k, cudaFuncAttributeMaxDynamicSharedMemorySize, ATTN_SMEM);
    cudaFuncSetAttribute(gemm_tc<true,  false, false, false>, cudaFuncAttributeMaxDynamicSharedMemorySize, GEMM_SMEM);
    cudaFuncSetAttribute(gemm_tc<false, true,  false, true >, cudaFuncAttributeMaxDynamicSharedMemorySize, GEMM_SMEM);
    cudaFuncSetAttribute(gemm_tc<true,  true,  true,  false>, cudaFuncAttributeMaxDynamicSharedMemorySize, GEMM_SMEM);

    dim3 tt(32, 8);
    transpose_k<<<dim3(CATD / 32, EMBED / 32), tt>>>(Wq, WQKV,                        EMBED, CATD, HEAD_DIM);
    transpose_k<<<dim3(CATD / 32, EMBED / 32), tt>>>(Wk, WQKV + (size_t)CATD * EMBED, EMBED, CATD, HEAD_DIM);
    transpose_k<<<dim3(CATD / 32, EMBED / 32), tt>>>(Wv, WQKV + (size_t)2 * CATD * EMBED, EMBED, CATD, HEAD_DIM);
    transpose_k<<<dim3(EMBED / 32, CATD / 32), tt>>>(Wo, WTO, CATD, EMBED, EMBED);
    transpose_k<<<dim3(FFN / 32, EMBED / 32),  tt>>>(W1, WT1, EMBED, FFN, FFN);
    transpose_k<<<dim3(EMBED / 32, FFN / 32),  tt>>>(W2, WT2, FFN, EMBED, EMBED);

    layernorm_k<<<NTOK, 256>>>(x, H, g1, be1);

    gemm_tc<true, false, false, false><<<dim3(QKVD / TILE_NF, NTOK / TILE_TK), 256, GEMM_SMEM>>>(
        WQKV, H, QKV, EMBED, QKVD, nullptr, nullptr);

    attention_k<<<BATCH * HEADS, 256, ATTN_SMEM>>>(QKV, O);

    gemm_tc<false, true, false, true><<<dim3(EMBED / TILE_NF, NTOK / TILE_TK), 256, GEMM_SMEM>>>(
        WTO, O, R, CATD, EMBED, bo, x);

    layernorm_k<<<NTOK, 256>>>(R, H, g2, be2);

    gemm_tc<true, true, true, false><<<dim3(FFN / TILE_NF, NTOK / TILE_TK), 256, GEMM_SMEM>>>(
        WT1, H, MID, EMBED, FFN, b1, nullptr);

    gemm_tc<false, true, false, true><<<dim3(EMBED / TILE_NF, NTOK / TILE_TK), 256, GEMM_SMEM>>>(
        WT2, MID, out, FFN, EMBED, b2, R);
}

// round 9
// speedup vs baseline: 1.3183x; 1.1513x over previous
#include <cuda_runtime.h>
#include <cuda_fp16.h>
#include <cstdint>

#define EMBED    768
#define HEADS    6
#define HEAD_DIM 256
#define SEQ      128
#define BATCH    512
#define NTOK     (BATCH * SEQ)        // 65536
#define CATD     (HEADS * HEAD_DIM)   // 1536
#define QKVD     (3 * CATD)           // 4608
#define FFN      (4 * EMBED)          // 3072

// ================= helpers =================
__device__ __forceinline__ uint32_t packh2(float lo, float hi) {
    uint32_t r;
    asm("cvt.rn.f16x2.f32 %0, %1, %2;" : "=r"(r) : "f"(hi), "f"(lo));
    return r;
}
__device__ __forceinline__ void mma16816(float* c, const uint32_t* a, const uint32_t* b) {
    asm volatile(
        "mma.sync.aligned.m16n8k16.row.col.f32.f16.f16.f32 "
        "{%0,%1,%2,%3}, {%4,%5,%6,%7}, {%8,%9}, {%0,%1,%2,%3};"
        : "+f"(c[0]), "+f"(c[1]), "+f"(c[2]), "+f"(c[3])
        : "r"(a[0]), "r"(a[1]), "r"(a[2]), "r"(a[3]), "r"(b[0]), "r"(b[1]));
}
__device__ __forceinline__ uint32_t smem_u32(const void* p) {
    uint32_t a;
    asm("{ .reg .u64 t; cvta.to.shared.u64 t, %1; cvt.u32.u64 %0, t; }" : "=r"(a) : "l"(p));
    return a;
}
#define CP_ASYNC16(saddr, gptr) \
    asm volatile("cp.async.cg.shared.global [%0], [%1], 16;" :: "r"(saddr), "l"(gptr))
#define CP_COMMIT() asm volatile("cp.async.commit_group;" ::: "memory")
#define CP_WAIT1()  asm volatile("cp.async.wait_group 1;" ::: "memory")
#define LDSM_X4(r0, r1, r2, r3, addr) \
    asm volatile("ldmatrix.sync.aligned.m8n8.x4.shared.b16 {%0,%1,%2,%3}, [%4];" \
        : "=r"(r0), "=r"(r1), "=r"(r2), "=r"(r3) : "r"(addr))

// GEMM tiling
#define TILE_NF  128
#define TILE_TK  256
#define KCH      64
#define HSTR     72                                    // halves per smem row (64 + 8 pad)
#define STAGES   3
#define STG_H    ((TILE_TK + TILE_NF) * HSTR)          // halves per stage
#define STG_B    (STG_H * 2)                           // bytes per stage (55296)
#define GEMM_SMEM (STAGES * STG_B)                     // 165888 B

// ================= scratch =================
__device__ __half g_hh  [(size_t)NTOK * EMBED];
__device__ __half g_qkv [(size_t)NTOK * QKVD];
__device__ __half g_oh  [(size_t)NTOK * CATD];
__device__ float  g_res [(size_t)NTOK * EMBED];
__device__ __half g_mid [(size_t)NTOK * FFN];
__device__ __half g_wqkv[(size_t)QKVD * EMBED];
__device__ __half g_wto [(size_t)EMBED * CATD];
__device__ __half g_wt1 [(size_t)FFN * EMBED];
__device__ __half g_wt2 [(size_t)EMBED * FFN];

// ================= transpose: in(k, n) -> out[n][k] (fp16 out) =================
__global__ __launch_bounds__(256) void transpose_k(
    const float* __restrict__ in, __half* __restrict__ out, int Kdim, int N, int Dh)
{
    __shared__ float t[32][33];
    const int k0 = blockIdx.y * 32;
    const int n0 = blockIdx.x * 32;
    const int tx = threadIdx.x, ty = threadIdx.y;

    #pragma unroll
    for (int i = 0; i < 4; i++) {
        const int k = k0 + ty + 8 * i;
        const int n = n0 + tx;
        const int h = n / Dh, d = n - h * Dh;
        t[ty + 8 * i][tx] = in[(size_t)h * Kdim * Dh + (size_t)k * Dh + d];
    }
    __syncthreads();
    #pragma unroll
    for (int i = 0; i < 4; i++) {
        out[(size_t)(n0 + ty + 8 * i) * Kdim + k0 + tx] = __float2half_rn(t[tx][ty + 8 * i]);
    }
}

// ================= LayerNorm (fp32 in -> fp16 out) =================
__global__ __launch_bounds__(256) void layernorm_k(
    const float* __restrict__ x, __half* __restrict__ y,
    const float* __restrict__ g, const float* __restrict__ b)
{
    const int row = blockIdx.x;
    const int tid = threadIdx.x;
    const float* xr = x + (size_t)row * EMBED;

    float v0 = xr[tid];
    float v1 = xr[tid + 256];
    float v2 = xr[tid + 512];

    float s = v0 + v1 + v2;
    float q = v0 * v0 + v1 * v1 + v2 * v2;

    #pragma unroll
    for (int o = 16; o; o >>= 1) {
        s += __shfl_xor_sync(0xffffffffu, s, o);
        q += __shfl_xor_sync(0xffffffffu, q, o);
    }
    __shared__ float ss[8], sq[8];
    const int w = tid >> 5, l = tid & 31;
    if (l == 0) { ss[w] = s; sq[w] = q; }
    __syncthreads();
    float S = 0.f, Q = 0.f;
    #pragma unroll
    for (int i = 0; i < 8; i++) { S += ss[i]; Q += sq[i]; }

    const float mu  = S * (1.0f / EMBED);
    const float var = Q * (1.0f / EMBED) - mu * mu;
    const float inv = rsqrtf(var + 1e-5f);

    __half* yr = y + (size_t)row * EMBED;
    yr[tid]       = __float2half_rn((v0 - mu) * inv * g[tid]       + b[tid]);
    yr[tid + 256] = __float2half_rn((v1 - mu) * inv * g[tid + 256] + b[tid + 256]);
    yr[tid + 512] = __float2half_rn((v2 - mu) * inv * g[tid + 512] + b[tid + 512]);
}

// ================= GEMM (fp16, 3-stage cp.async, ldmatrix fragments) =================
// C[m,n] = sum_k Hm[m,k]*Wt[n,k] (+bias)(relu)(+res)
template<bool OUT16, bool BIAS, bool RELU, bool RES>
__global__ __launch_bounds__(256) void gemm_tc(
    const __half* __restrict__ Wt,   // [Nout, K]  K-major fp16
    const __half* __restrict__ Hm,   // [NTOK, K]  fp16
    void* __restrict__ Cout,         // fp16 or fp32 [NTOK, Nout]
    int K, int Nout,
    const float* __restrict__ bias,
    const float* __restrict__ res)
{
    extern __shared__ char smem[];
    const uint32_t sb32 = smem_u32(smem);

    const int tid = threadIdx.x;
    const int wid = tid >> 5, lid = tid & 31;
    const int g = lid >> 2, t = lid & 3;
    const int wm = wid & 3;
    const int wn = wid >> 2;

    const int n0 = blockIdx.x * TILE_NF;
    const int m0 = blockIdx.y * TILE_TK;
    const int chunks = K / KCH;

    const __half* Ag = Hm + (size_t)m0 * K;
    const __half* Bg = Wt + (size_t)n0 * K;

    // cp.async coords: A rows 0..255 (8 x 16B per row), B rows 0..127
    const int arow = tid >> 3, aq = tid & 7;

    // ldmatrix lane offsets (halves -> *2 bytes at use)
    const uint32_t a_lane = (uint32_t)(((lid & 15) * HSTR + ((lid >> 4) << 3)) * 2);
    const uint32_t b_lane = (uint32_t)((((lid & 7) + ((lid >> 4) << 3)) * HSTR + ((lid >> 3) & 1) * 8) * 2);

    float acc[4][8][4];
    #pragma unroll
    for (int i = 0; i < 4; i++)
        #pragma unroll
        for (int j = 0; j < 8; j++)
            #pragma unroll
            for (int r = 0; r < 4; r++) acc[i][j][r] = 0.f;

    // issue one 64-K chunk into a stage (12 x cp.async 16B per thread)
    #define ISSUE_CHUNK(chunk, stg) do { \
        const int kofs_ = (chunk) * KCH; \
        const uint32_t sA_ = sb32 + (stg) * STG_B; \
        const uint32_t sB_ = sA_ + TILE_TK * HSTR * 2; \
        _Pragma("unroll") \
        for (int i = 0; i < 8; i++) \
            CP_ASYNC16(sA_ + (((arow + 32 * i) * HSTR + aq * 8) * 2), \
                       Ag + (size_t)(arow + 32 * i) * K + kofs_ + aq * 8); \
        _Pragma("unroll") \
        for (int i = 0; i < 4; i++) \
            CP_ASYNC16(sB_ + (((arow + 32 * i) * HSTR + aq * 8) * 2), \
                       Bg + (size_t)(arow + 32 * i) * K + kofs_ + aq * 8); \
    } while (0)

    ISSUE_CHUNK(0, 0); CP_COMMIT();
    if (chunks > 1) { ISSUE_CHUNK(1, 1); } CP_COMMIT();

    for (int c = 0; c < chunks; c++) {
        CP_WAIT1();
        __syncthreads();

        if (c + STAGES - 1 < chunks) { ISSUE_CHUNK(c + STAGES - 1, (c + STAGES - 1) % STAGES); }
        CP_COMMIT();

        const uint32_t sA32 = sb32 + (c % STAGES) * STG_B;
        const uint32_t sB32 = sA32 + TILE_TK * HSTR * 2;

        #pragma unroll
        for (int ks = 0; ks < 4; ks++) {
            const int kb = ks * 16;
            uint32_t af[4][4];
            #pragma unroll
            for (int mt = 0; mt < 4; mt++) {
                const uint32_t addr = sA32 + (uint32_t)(((wm * 64 + mt * 16) * HSTR + kb) * 2) + a_lane;
                LDSM_X4(af[mt][0], af[mt][1], af[mt][2], af[mt][3], addr);
            }
            uint32_t bf[8][2];
            #pragma unroll
            for (int ntp = 0; ntp < 4; ntp++) {
                const uint32_t addr = sB32 + (uint32_t)(((wn * 64 + ntp * 16) * HSTR + kb) * 2) + b_lane;
                LDSM_X4(bf[2 * ntp][0], bf[2 * ntp][1], bf[2 * ntp + 1][0], bf[2 * ntp + 1][1], addr);
            }
            #pragma unroll
            for (int mt = 0; mt < 4; mt++)
                #pragma unroll
                for (int nt = 0; nt < 8; nt++)
                    mma16816(acc[mt][nt], af[mt], bf[nt]);
        }
    }
    #undef ISSUE_CHUNK

    float* C32 = reinterpret_cast<float*>(Cout);
    __half* C16 = reinterpret_cast<__half*>(Cout);

    #pragma unroll
    for (int mt = 0; mt < 4; mt++) {
        #pragma unroll
        for (int nt = 0; nt < 8; nt++) {
            const int col = n0 + wn * 64 + nt * 8 + 2 * t;
            float bx = 0.f, by = 0.f;
            if (BIAS) {
                const float2 b2 = *reinterpret_cast<const float2*>(bias + col);
                bx = b2.x; by = b2.y;
            }
            const int r1 = m0 + wm * 64 + mt * 16 + g;
            const int r2 = r1 + 8;

            float2 v1, v2;
            v1.x = acc[mt][nt][0] + bx; v1.y = acc[mt][nt][1] + by;
            v2.x = acc[mt][nt][2] + bx; v2.y = acc[mt][nt][3] + by;
            if (RELU) {
                v1.x = fmaxf(v1.x, 0.f); v1.y = fmaxf(v1.y, 0.f);
                v2.x = fmaxf(v2.x, 0.f); v2.y = fmaxf(v2.y, 0.f);
            }
            if (RES) {
                const float2 r1v = *reinterpret_cast<const float2*>(res + (size_t)r1 * Nout + col);
                const float2 r2v = *reinterpret_cast<const float2*>(res + (size_t)r2 * Nout + col);
                v1.x += r1v.x; v1.y += r1v.y;
                v2.x += r2v.x; v2.y += r2v.y;
            }
            if (OUT16) {
                *reinterpret_cast<uint32_t*>(C16 + (size_t)r1 * Nout + col) = packh2(v1.x, v1.y);
                *reinterpret_cast<uint32_t*>(C16 + (size_t)r2 * Nout + col) = packh2(v2.x, v2.y);
            } else {
                *reinterpret_cast<float2*>(C32 + (size_t)r1 * Nout + col) = v1;
                *reinterpret_cast<float2*>(C32 + (size_t)r2 * Nout + col) = v2;
            }
        }
    }
}

// ================= tensor-core causal attention =================
#define PSTR 136
#define QSTR 72
#define SSTR 132
#define VSTR 130
#define ATTN_SMEM (128 * PSTR * 2 + 128 * SSTR * 4)   // 102400

__global__ __launch_bounds__(256) void attention_k(
    const __half* __restrict__ qkv,   // [NTOK][4608]
    __half* __restrict__ o)           // [NTOK][1536]
{
    extern __shared__ char smem[];
    uint16_t* sP = reinterpret_cast<uint16_t*>(smem);
    char* ws = smem + 128 * PSTR * 2;
    uint16_t* sQ = reinterpret_cast<uint16_t*>(ws);
    uint16_t* sK = sQ + 128 * QSTR;
    float*    sS = reinterpret_cast<float*>(ws);
    uint16_t* sVt = reinterpret_cast<uint16_t*>(ws);

    const int tid = threadIdx.x;
    const int wid = tid >> 5, lid = tid & 31;
    const int g = lid >> 2, t = lid & 3;
    const int wm = wid & 3;
    const int wn = wid >> 2;

    const int bh = blockIdx.x;
    const int b  = bh / HEADS;
    const int h  = bh - b * HEADS;

    const __half* qbase = qkv + (size_t)(b * SEQ) * QKVD + h * HEAD_DIM;
    const __half* kbase = qbase + CATD;
    const __half* vbase = qbase + 2 * CATD;
    __half* obase = o + (size_t)(b * SEQ) * CATD + h * HEAD_DIM;

    // ---- S = Q K^T ----
    float acc[2][8][4];
    #pragma unroll
    for (int i = 0; i < 2; i++)
        #pragma unroll
        for (int j = 0; j < 8; j++)
            #pragma unroll
            for (int r = 0; r < 4; r++) acc[i][j][r] = 0.f;

    for (int c = 0; c < 4; c++) {
        #pragma unroll
        for (int i = 0; i < 4; i++) {
            const int idx = tid + 256 * i, row = idx >> 3, q = idx & 7;
            *reinterpret_cast<uint4*>(sQ + row * QSTR + q * 8) =
                *reinterpret_cast<const uint4*>(qbase + (size_t)row * QKVD + c * 64 + q * 8);
            *reinterpret_cast<uint4*>(sK + row * QSTR + q * 8) =
                *reinterpret_cast<const uint4*>(kbase + (size_t)row * QKVD + c * 64 + q * 8);
        }
        __syncthreads();

        #pragma unroll
        for (int ks = 0; ks < 4; ks++) {
            const int kb = ks * 16;
            uint32_t af[2][4];
            #pragma unroll
            for (int mt = 0; mt < 2; mt++) {
                const int rb = wm * 32 + mt * 16;
                af[mt][0] = *reinterpret_cast<const uint32_t*>(&sQ[(rb + g)     * QSTR + kb + 2 * t]);
                af[mt][1] = *reinterpret_cast<const uint32_t*>(&sQ[(rb + g + 8) * QSTR + kb + 2 * t]);
                af[mt][2] = *reinterpret_cast<const uint32_t*>(&sQ[(rb + g)     * QSTR + kb + 2 * t + 8]);
                af[mt][3] = *reinterpret_cast<const uint32_t*>(&sQ[(rb + g + 8) * QSTR + kb + 2 * t + 8]);
            }
            #pragma unroll
            for (int nt = 0; nt < 8; nt++) {
                if (wn * 64 + nt * 8 <= wm * 32 + 31) {
                    const int cb = wn * 64 + nt * 8 + g;
                    uint32_t bf[2];
                    bf[0] = *reinterpret_cast<const uint32_t*>(&sK[cb * QSTR + kb + 2 * t]);
                    bf[1] = *reinterpret_cast<const uint32_t*>(&sK[cb * QSTR + kb + 2 * t + 8]);
                    #pragma unroll
                    for (int mt = 0; mt < 2; mt++)
                        mma16816(acc[mt][nt], af[mt], bf);
                }
            }
        }
        __syncthreads();
    }

    // ---- scaled S -> smem ----
    const float scale = 0.03608439182435161f; // 768^-0.5
    #pragma unroll
    for (int mt = 0; mt < 2; mt++) {
        #pragma unroll
        for (int nt = 0; nt < 8; nt++) {
            const int col = wn * 64 + nt * 8 + 2 * t;
            const int r1 = wm * 32 + mt * 16 + g;
            float2 v1, v2;
            v1.x = acc[mt][nt][0] * scale; v1.y = acc[mt][nt][1] * scale;
            v2.x = acc[mt][nt][2] * scale; v2.y = acc[mt][nt][3] * scale;
            *reinterpret_cast<float2*>(sS + (r1)     * SSTR + col) = v1;
            *reinterpret_cast<float2*>(sS + (r1 + 8) * SSTR + col) = v2;
        }
    }
    __syncthreads();

    // ---- softmax: one warp per row (8 warps x 16 rows), writes P fp16 incl. zero fill ----
    for (int rr = wid; rr < 128; rr += 8) {
        const float* row = sS + rr * SSTR;
        float mx = -1e30f;
        #pragma unroll
        for (int i = 0; i < 4; i++) {
            const int s = lid + 32 * i;
            if (s <= rr) mx = fmaxf(mx, row[s]);
        }
        #pragma unroll
        for (int o2 = 16; o2; o2 >>= 1) mx = fmaxf(mx, __shfl_xor_sync(0xffffffffu, mx, o2));

        float e[4];
        float sum = 0.f;
        #pragma unroll
        for (int i = 0; i < 4; i++) {
            const int s = lid + 32 * i;
            e[i] = (s <= rr) ? __expf(row[s] - mx) : 0.f;
            sum += e[i];
        }
        #pragma unroll
        for (int o2 = 16; o2; o2 >>= 1) sum += __shfl_xor_sync(0xffffffffu, sum, o2);
        const float inv = 1.0f / sum;

        uint16_t* prow = sP + rr * PSTR;
        #pragma unroll
        for (int i = 0; i < 4; i++) {
            const int s = lid + 32 * i;
            const __half hv = __float2half_rn(e[i] * inv);
            prow[s] = *reinterpret_cast<const uint16_t*>(&hv);
        }
    }
    __syncthreads();

    // ---- O = P V ----
    for (int c = 0; c < 4; c++) {
        #pragma unroll
        for (int i = 0; i < 16; i++) {
            const int id = tid + 256 * i;
            const int s = id >> 5, d2 = id & 31;
            const uint32_t v2 = *reinterpret_cast<const uint32_t*>(
                vbase + (size_t)s * QKVD + c * 64 + 2 * d2);
            sVt[(2 * d2)     * VSTR + s] = (uint16_t)(v2 & 0xffffu);
            sVt[(2 * d2 + 1) * VSTR + s] = (uint16_t)(v2 >> 16);
        }
        __syncthreads();

        float oacc[2][4][4];
        #pragma unroll
        for (int i = 0; i < 2; i++)
            #pragma unroll
            for (int j = 0; j < 4; j++)
                #pragma unroll
                for (int r = 0; r < 4; r++) oacc[i][j][r] = 0.f;

        #pragma unroll
        for (int ks = 0; ks < 8; ks++) {
            if (ks * 16 > wm * 32 + 31) break;
            const int kb = ks * 16;
            uint32_t af[2][4];
            #pragma unroll
            for (int mt = 0; mt < 2; mt++) {
                const int rb = wm * 32 + mt * 16;
                af[mt][0] = *reinterpret_cast<const uint32_t*>(&sP[(rb + g)     * PSTR + kb + 2 * t]);
                af[mt][1] = *reinterpret_cast<const uint32_t*>(&sP[(rb + g + 8) * PSTR + kb + 2 * t]);
                af[mt][2] = *reinterpret_cast<const uint32_t*>(&sP[(rb + g)     * PSTR + kb + 2 * t + 8]);
                af[mt][3] = *reinterpret_cast<const uint32_t*>(&sP[(rb + g + 8) * PSTR + kb + 2 * t + 8]);
            }
            #pragma unroll
            for (int nt = 0; nt < 4; nt++) {
                const int cb = wn * 32 + nt * 8 + g;
                uint32_t bf[2];
                bf[0] = *reinterpret_cast<const uint32_t*>(&sVt[cb * VSTR + kb + 2 * t]);
                bf[1] = *reinterpret_cast<const uint32_t*>(&sVt[cb * VSTR + kb + 2 * t + 8]);
                #pragma unroll
                for (int mt = 0; mt < 2; mt++)
                    mma16816(oacc[mt][nt], af[mt], bf);
            }
        }

        #pragma unroll
        for (int mt = 0; mt < 2; mt++) {
            #pragma unroll
            for (int nt = 0; nt < 4; nt++) {
                const int d = c * 64 + wn * 32 + nt * 8 + 2 * t;
                const int r1 = wm * 32 + mt * 16 + g;
                *reinterpret_cast<uint32_t*>(obase + (size_t)r1 * CATD + d) =
                    packh2(oacc[mt][nt][0], oacc[mt][nt][1]);
                *reinterpret_cast<uint32_t*>(obase + (size_t)(r1 + 8) * CATD + d) =
                    packh2(oacc[mt][nt][2], oacc[mt][nt][3]);
            }
        }
        __syncthreads();
    }
}

// ================= launch =================
extern "C" void kernel_launch(void* const* d_in, const int* in_sizes, int n_in,
                              void* d_out, int out_size)
{
    const float* x   = (const float*)d_in[0];
    const float* Wq  = (const float*)d_in[1];
    const float* Wk  = (const float*)d_in[2];
    const float* Wv  = (const float*)d_in[3];
    const float* Wo  = (const float*)d_in[4];
    const float* bo  = (const float*)d_in[5];
    const float* W1  = (const float*)d_in[6];
    const float* b1  = (const float*)d_in[7];
    const float* W2  = (const float*)d_in[8];
    const float* b2  = (const float*)d_in[9];
    const float* g1  = (const float*)d_in[10];
    const float* be1 = (const float*)d_in[11];
    const float* g2  = (const float*)d_in[12];
    const float* be2 = (const float*)d_in[13];
    float* out = (float*)d_out;

    void *phh, *pqkv, *poh, *pres, *pmid, *pwqkv, *pwto, *pwt1, *pwt2;
    cudaGetSymbolAddress(&phh,  g_hh);
    cudaGetSymbolAddress(&pqkv, g_qkv);
    cudaGetSymbolAddress(&poh,  g_oh);
    cudaGetSymbolAddress(&pres, g_res);
    cudaGetSymbolAddress(&pmid, g_mid);
    cudaGetSymbolAddress(&pwqkv, g_wqkv);
    cudaGetSymbolAddress(&pwto, g_wto);
    cudaGetSymbolAddress(&pwt1, g_wt1);
    cudaGetSymbolAddress(&pwt2, g_wt2);
    __half* H    = (__half*)phh;
    __half* QKV  = (__half*)pqkv;
    __half* O    = (__half*)poh;
    float*  R    = (float*)pres;
    __half* MID  = (__half*)pmid;
    __half* WQKV = (__half*)pwqkv;
    __half* WTO  = (__half*)pwto;
    __half* WT1  = (__half*)pwt1;
    __half* WT2  = (__half*)pwt2;

    cudaFuncSetAttribute(attention_k, cudaFuncAttributeMaxDynamicSharedMemorySize, ATTN_SMEM);
    cudaFuncSetAttribute(gemm_tc<true,  false, false, false>, cudaFuncAttributeMaxDynamicSharedMemorySize, GEMM_SMEM);
    cudaFuncSetAttribute(gemm_tc<false, true,  false, true >, cudaFuncAttributeMaxDynamicSharedMemorySize, GEMM_SMEM);
    cudaFuncSetAttribute(gemm_tc<true,  true,  true,  false>, cudaFuncAttributeMaxDynamicSharedMemorySize, GEMM_SMEM);

    dim3 tt(32, 8);
    transpose_k<<<dim3(CATD / 32, EMBED / 32), tt>>>(Wq, WQKV,                        EMBED, CATD, HEAD_DIM);
    transpose_k<<<dim3(CATD / 32, EMBED / 32), tt>>>(Wk, WQKV + (size_t)CATD * EMBED, EMBED, CATD, HEAD_DIM);
    transpose_k<<<dim3(CATD / 32, EMBED / 32), tt>>>(Wv, WQKV + (size_t)2 * CATD * EMBED, EMBED, CATD, HEAD_DIM);
    transpose_k<<<dim3(EMBED / 32, CATD / 32), tt>>>(Wo, WTO, CATD, EMBED, EMBED);
    transpose_k<<<dim3(FFN / 32, EMBED / 32),  tt>>>(W1, WT1, EMBED, FFN, FFN);
    transpose_k<<<dim3(EMBED / 32, FFN / 32),  tt>>>(W2, WT2, FFN, EMBED, EMBED);

    layernorm_k<<<NTOK, 256>>>(x, H, g1, be1);

    gemm_tc<true, false, false, false><<<dim3(QKVD / TILE_NF, NTOK / TILE_TK), 256, GEMM_SMEM>>>(
        WQKV, H, QKV, EMBED, QKVD, nullptr, nullptr);

    attention_k<<<BATCH * HEADS, 256, ATTN_SMEM>>>(QKV, O);

    gemm_tc<false, true, false, true><<<dim3(EMBED / TILE_NF, NTOK / TILE_TK), 256, GEMM_SMEM>>>(
        WTO, O, R, CATD, EMBED, bo, x);

    layernorm_k<<<NTOK, 256>>>(R, H, g2, be2);

    gemm_tc<true, true, true, false><<<dim3(FFN / TILE_NF, NTOK / TILE_TK), 256, GEMM_SMEM>>>(
        WT1, H, MID, EMBED, FFN, b1, nullptr);

    gemm_tc<false, true, false, true><<<dim3(EMBED / TILE_NF, NTOK / TILE_TK), 256, GEMM_SMEM>>>(
        WT2, MID, out, FFN, EMBED, b2, R);
}